// round 15
// baseline (speedup 1.0000x reference)
#include <cuda_runtime.h>

#define Hh 100
#define Ww 136
#define HW (Hh * Ww)        // 13600
#define OH (2 * Hh)         // 200
#define OW (2 * Ww)         // 272
#define OHW (OH * OW)       // 54400
#define NP 169
#define MAXI 512
#define NBANDS 8            // output-row bands per instance
#define BAND_OH 25          // output rows per band
#define MAX_ROWS 14         // max logit rows a band needs
#define NT 128              // threads per fused block (4 blocks/SM)

typedef unsigned long long ull;

// per-(instance,band) dice partials
__device__ float g_pi[MAXI * NBANDS];
__device__ float g_px[MAXI * NBANDS];
__device__ float g_pt[MAXI * NBANDS];

// ---- packed f32x2 helpers (sm_100+) ----
__device__ __forceinline__ ull pk2(float lo, float hi) {
    ull r; asm("mov.b64 %0, {%1,%2};" : "=l"(r) : "f"(lo), "f"(hi)); return r;
}
__device__ __forceinline__ ull fma2(ull a, ull b, ull c) {
    ull d; asm("fma.rn.f32x2 %0, %1, %2, %3;" : "=l"(d) : "l"(a), "l"(b), "l"(c)); return d;
}
__device__ __forceinline__ ull relu2(ull a) {
    float x, y;
    asm("mov.b64 {%0,%1}, %2;" : "=f"(x), "=f"(y) : "l"(a));
    x = fmaxf(x, 0.0f); y = fmaxf(y, 0.0f);
    ull r; asm("mov.b64 %0, {%1,%2};" : "=l"(r) : "f"(x), "f"(y)); return r;
}
__device__ __forceinline__ void upk2(ull a, float& x, float& y) {
    asm("mov.b64 {%0,%1}, %2;" : "=f"(x), "=f"(y) : "l"(a));
}
__device__ __forceinline__ float tanh_fast(float x) {
    float r; asm("tanh.approx.f32 %0, %1;" : "=f"(r) : "f"(x)); return r;
}

// ---------------------------------------------------------------------------
// Fused kernel: one block = one (instance, band). 128 threads, 4 blocks/SM.
// NBANDS=8 -> grid 4000 -> 7 waves at 96.5% efficiency (was 3.38 @ 84.5%).
//   Phase 1: MLP logits for the band's <=14 rows into SMEM (proven body).
//   Phase 2: 2x aligned bilinear + sigmoid(tanh) + dice partials, 16-px
//            units with vectorized (LDS.128) tap loads.
// ---------------------------------------------------------------------------
__global__ __launch_bounds__(NT, 4) void fused_kernel(
    const float* __restrict__ feats,
    const float* __restrict__ params,
    const float* __restrict__ locs,
    const int*   __restrict__ im_inds,
    const int*   __restrict__ fpn,
    const float* __restrict__ gt)
{
    const int inst = blockIdx.x >> 3;
    const int band = blockIdx.x & 7;
    const int tid  = threadIdx.x;

    extern __shared__ float sL[];              // MAX_ROWS * Ww floats

    __shared__ __align__(16) ull sw0[8][12];   // [j][0..9]=w, [10]=bias
    __shared__ __align__(16) ull sw1[8][10];   // [j][0..7]=w, [8]=bias
    __shared__ __align__(16) ull sw2[10];      // [0..7]=w,   [8]=bias

    for (int i = tid; i < NP; i += NT) {
        float w = params[inst * NP + i];
        ull d = pk2(w, w);
        if      (i < 80)  sw0[i / 10][i % 10] = d;
        else if (i < 144) { int k = i - 80; sw1[k >> 3][k & 7] = d; }
        else if (i < 152) sw2[i - 144] = d;
        else if (i < 160) sw0[i - 152][10] = d;
        else if (i < 168) sw1[i - 160][8] = d;
        else              sw2[8] = d;
    }
    __syncthreads();

    // band geometry (generic)
    const int oy0 = band * BAND_OH;                        // first output row
    const int ry0 = (oy0 > 0) ? ((oy0 - 1) >> 1) : 0;      // first logit row
    int ry1 = ((oy0 + BAND_OH - 2) >> 1) + 1;              // last logit row
    if (ry1 > Hh - 1) ry1 = Hh - 1;
    const int nrows = ry1 - ry0 + 1;                       // <= 14

    const float cx = locs[inst * 2 + 0];
    const float cy = locs[inst * 2 + 1];
    const float inv_soi = 1.0f / (float)(8 << fpn[inst]);
    const float step = -8.0f * inv_soi;
    const float* __restrict__ fb = feats + (size_t)im_inds[inst] * 8 * HW;

    // ---------------- Phase 1: logits for rows [ry0..ry1] into SMEM --------
    const int NQ = nrows * (Ww / 4);        // <= 14*34 = 476 quads
    for (int q = tid; q < NQ; q += NT) {
        const int lr = q / (Ww / 4);
        const int px = (q - lr * (Ww / 4)) * 4;
        const int py = ry0 + lr;
        const int p  = py * Ww + px;
        const float dyv = (cy - (float)(py * 8 + 4)) * inv_soi;
        const float dxb = (cx - (float)(px * 8 + 4)) * inv_soi;
        const ull dy2 = pk2(dyv, dyv);
        const ull dx0 = pk2(dxb, dxb + step);
        const ull dx1 = pk2(dxb + 2.0f * step, dxb + 3.0f * step);

        ull f0[8], f1[8];
        #pragma unroll
        for (int c = 0; c < 8; c++) {
            float4 v = *(const float4*)&fb[c * HW + p];
            f0[c] = pk2(v.x, v.y);
            f1[c] = pk2(v.z, v.w);
        }

        // layer 0: 10 -> 8, relu
        ull h0a[8], h0b[8];
        #pragma unroll
        for (int j = 0; j < 8; j++) {
            const ulonglong2* r = (const ulonglong2*)sw0[j];
            ulonglong2 wA = r[0], wB = r[1], wC = r[2], wD = r[3], wE = r[4];
            ull bias = sw0[j][10];
            ull ty = fma2(wA.y, dy2, bias);
            ull a0 = fma2(wA.x, dx0, ty);
            ull a1 = fma2(wA.x, dx1, ty);
            a0 = fma2(wB.x, f0[0], a0);  a1 = fma2(wB.x, f1[0], a1);
            a0 = fma2(wB.y, f0[1], a0);  a1 = fma2(wB.y, f1[1], a1);
            a0 = fma2(wC.x, f0[2], a0);  a1 = fma2(wC.x, f1[2], a1);
            a0 = fma2(wC.y, f0[3], a0);  a1 = fma2(wC.y, f1[3], a1);
            a0 = fma2(wD.x, f0[4], a0);  a1 = fma2(wD.x, f1[4], a1);
            a0 = fma2(wD.y, f0[5], a0);  a1 = fma2(wD.y, f1[5], a1);
            a0 = fma2(wE.x, f0[6], a0);  a1 = fma2(wE.x, f1[6], a1);
            a0 = fma2(wE.y, f0[7], a0);  a1 = fma2(wE.y, f1[7], a1);
            h0a[j] = relu2(a0);
            h0b[j] = relu2(a1);
        }

        // layer 1: 8 -> 8, relu
        ull h1a[8], h1b[8];
        #pragma unroll
        for (int j = 0; j < 8; j++) {
            const ulonglong2* r = (const ulonglong2*)sw1[j];
            ulonglong2 wA = r[0], wB = r[1], wC = r[2], wD = r[3];
            ull bias = sw1[j][8];
            ull a0 = fma2(wA.x, h0a[0], bias);  ull a1 = fma2(wA.x, h0b[0], bias);
            a0 = fma2(wA.y, h0a[1], a0);  a1 = fma2(wA.y, h0b[1], a1);
            a0 = fma2(wB.x, h0a[2], a0);  a1 = fma2(wB.x, h0b[2], a1);
            a0 = fma2(wB.y, h0a[3], a0);  a1 = fma2(wB.y, h0b[3], a1);
            a0 = fma2(wC.x, h0a[4], a0);  a1 = fma2(wC.x, h0b[4], a1);
            a0 = fma2(wC.y, h0a[5], a0);  a1 = fma2(wC.y, h0b[5], a1);
            a0 = fma2(wD.x, h0a[6], a0);  a1 = fma2(wD.x, h0b[6], a1);
            a0 = fma2(wD.y, h0a[7], a0);  a1 = fma2(wD.y, h0b[7], a1);
            h1a[j] = relu2(a0);
            h1b[j] = relu2(a1);
        }

        // layer 2: 8 -> 1
        {
            const ulonglong2* r = (const ulonglong2*)sw2;
            ulonglong2 wA = r[0], wB = r[1], wC = r[2], wD = r[3];
            ull bias = sw2[8];
            ull a0 = fma2(wA.x, h1a[0], bias);  ull a1 = fma2(wA.x, h1b[0], bias);
            a0 = fma2(wA.y, h1a[1], a0);  a1 = fma2(wA.y, h1b[1], a1);
            a0 = fma2(wB.x, h1a[2], a0);  a1 = fma2(wB.x, h1b[2], a1);
            a0 = fma2(wB.y, h1a[3], a0);  a1 = fma2(wB.y, h1b[3], a1);
            a0 = fma2(wC.x, h1a[4], a0);  a1 = fma2(wC.x, h1b[4], a1);
            a0 = fma2(wC.y, h1a[5], a0);  a1 = fma2(wC.y, h1b[5], a1);
            a0 = fma2(wD.x, h1a[6], a0);  a1 = fma2(wD.x, h1b[6], a1);
            a0 = fma2(wD.y, h1a[7], a0);  a1 = fma2(wD.y, h1b[7], a1);
            float4 o;
            upk2(a0, o.x, o.y);
            upk2(a1, o.z, o.w);
            *(float4*)&sL[lr * Ww + px] = o;
        }

        // Anti-pipelining fence (R7 win: keeps regs bounded, no spill).
        asm volatile("" ::: "memory");
    }
    __syncthreads();

    // ---------------- Phase 2: bilinear + sigmoid + dice on the band -------
    const float* __restrict__ T = gt + (size_t)inst * OHW;
    float si = 0.0f, sx = 0.0f, st = 0.0f;

    const int NU = BAND_OH * (OW / 16);    // 25*17 = 425 units per block
    for (int u = tid; u < NU; u += NT) {
        const int r    = u / (OW / 16);
        const int ox16 = (u - r * (OW / 16)) * 16;
        const int oy   = oy0 + r;
        const int j    = (oy > 0) ? (oy - 1) : 0;
        const int y0g  = j >> 1;
        const float* r0 = sL + (y0g - ry0) * Ww;

        const int m0 = ox16 >> 1;                 // multiple of 8; m0+7 <= 135
        const int ml = (m0 > 0) ? m0 - 1 : 0;

        float t[9];                               // taps m0-1 .. m0+7
        if ((j & 1) == 0) {
            float4 a = *(const float4*)&r0[m0];
            float4 b = *(const float4*)&r0[m0 + 4];
            t[0] = r0[ml];
            t[1] = a.x; t[2] = a.y; t[3] = a.z; t[4] = a.w;
            t[5] = b.x; t[6] = b.y; t[7] = b.z; t[8] = b.w;
        } else {
            const int y1g = (y0g + 1 < Hh) ? y0g + 1 : Hh - 1;
            const float* r1 = sL + (y1g - ry0) * Ww;
            float4 a0 = *(const float4*)&r0[m0];
            float4 a1 = *(const float4*)&r1[m0];
            float4 b0 = *(const float4*)&r0[m0 + 4];
            float4 b1 = *(const float4*)&r1[m0 + 4];
            t[0] = 0.5f * (r0[ml] + r1[ml]);
            t[1] = 0.5f * (a0.x + a1.x); t[2] = 0.5f * (a0.y + a1.y);
            t[3] = 0.5f * (a0.z + a1.z); t[4] = 0.5f * (a0.w + a1.w);
            t[5] = 0.5f * (b0.x + b1.x); t[6] = 0.5f * (b0.y + b1.y);
            t[7] = 0.5f * (b0.z + b1.z); t[8] = 0.5f * (b0.w + b1.w);
        }

        float v[16];
        v[0] = (ox16 > 0) ? 0.5f * (t[0] + t[1]) : t[1];
        #pragma unroll
        for (int i = 1; i < 8; i++) v[2 * i] = 0.5f * (t[i] + t[i + 1]);
        #pragma unroll
        for (int i = 0; i < 8; i++) v[2 * i + 1] = t[i + 1];

        const int gbase = oy * OW + ox16;
        #pragma unroll
        for (int c = 0; c < 4; c++) {
            const float4 g = __ldcs((const float4*)&T[gbase + 4 * c]);
            const float tv[4] = { g.x, g.y, g.z, g.w };
            #pragma unroll
            for (int k = 0; k < 4; k++) {
                float s = fmaf(0.5f, tanh_fast(0.5f * v[4 * c + k]), 0.5f);
                si = fmaf(s, tv[k], si);
                sx = fmaf(s, s, sx);
                st = fmaf(tv[k], tv[k], st);
            }
        }
    }

    // block reduction (4 warps) -> per-(inst,band) partials
    __shared__ float sm[3][4];
    int lane = tid & 31;
    int wid  = tid >> 5;
    #pragma unroll
    for (int o = 16; o; o >>= 1) {
        si += __shfl_down_sync(0xffffffffu, si, o);
        sx += __shfl_down_sync(0xffffffffu, sx, o);
        st += __shfl_down_sync(0xffffffffu, st, o);
    }
    if (lane == 0) { sm[0][wid] = si; sm[1][wid] = sx; sm[2][wid] = st; }
    __syncthreads();
    if (wid == 0) {
        si = (lane < 4) ? sm[0][lane] : 0.0f;
        sx = (lane < 4) ? sm[1][lane] : 0.0f;
        st = (lane < 4) ? sm[2][lane] : 0.0f;
        #pragma unroll
        for (int o = 2; o; o >>= 1) {
            si += __shfl_down_sync(0xffffffffu, si, o);
            sx += __shfl_down_sync(0xffffffffu, sx, o);
            st += __shfl_down_sync(0xffffffffu, st, o);
        }
        if (lane == 0) {
            g_pi[blockIdx.x] = si;
            g_px[blockIdx.x] = sx;
            g_pt[blockIdx.x] = st;
        }
    }
}

// ---------------------------------------------------------------------------
// Loss: PDL — resident early, waits on the fused grid, then reduces.
// ---------------------------------------------------------------------------
__global__ __launch_bounds__(512) void loss_kernel(float* __restrict__ out, int n)
{
    cudaGridDependencySynchronize();   // PDL: wait for fused_kernel completion

    __shared__ float sm[16];
    float acc = 0.0f;
    for (int i = threadIdx.x; i < n; i += 512) {
        float si = 0.0f, sx = 0.0f, st = 0.0f;
        #pragma unroll
        for (int b = 0; b < NBANDS; b++) {
            si += g_pi[i * NBANDS + b];
            sx += g_px[i * NBANDS + b];
            st += g_pt[i * NBANDS + b];
        }
        float u = sx + st + 1e-5f;
        acc += 1.0f - 2.0f * si / u;
    }
    int lane = threadIdx.x & 31;
    int wid  = threadIdx.x >> 5;
    #pragma unroll
    for (int o = 16; o; o >>= 1) acc += __shfl_down_sync(0xffffffffu, acc, o);
    if (lane == 0) sm[wid] = acc;
    __syncthreads();
    if (wid == 0) {
        acc = (lane < 16) ? sm[lane] : 0.0f;
        #pragma unroll
        for (int o = 8; o; o >>= 1) acc += __shfl_down_sync(0xffffffffu, acc, o);
        if (lane == 0) out[0] = acc / (float)n;
    }
}

extern "C" void kernel_launch(void* const* d_in, const int* in_sizes, int n_in,
                              void* d_out, int out_size)
{
    const float* feats   = (const float*)d_in[0];
    const float* params  = (const float*)d_in[1];
    const float* locs    = (const float*)d_in[2];
    const float* gt      = (const float*)d_in[3];
    const int*   im_inds = (const int*)d_in[4];
    const int*   fpn     = (const int*)d_in[5];

    int n = in_sizes[1] / NP;
    if (n > MAXI) n = MAXI;

    const int smem = MAX_ROWS * Ww * (int)sizeof(float);   // 7616 B

    fused_kernel<<<NBANDS * n, NT, smem>>>(feats, params, locs, im_inds, fpn, gt);

    // PDL launch: loss_kernel becomes resident during fused tail.
    cudaLaunchConfig_t cfg = {};
    cfg.gridDim  = dim3(1, 1, 1);
    cfg.blockDim = dim3(512, 1, 1);
    cudaLaunchAttribute attr[1];
    attr[0].id = cudaLaunchAttributeProgrammaticStreamSerialization;
    attr[0].val.programmaticStreamSerializationAllowed = 1;
    cfg.attrs = attr;
    cfg.numAttrs = 1;
    cudaLaunchKernelEx(&cfg, loss_kernel, (float*)d_out, n);
}

// round 16
// speedup vs baseline: 1.2600x; 1.2600x over previous
#include <cuda_runtime.h>

#define Hh 100
#define Ww 136
#define HW (Hh * Ww)        // 13600
#define OH (2 * Hh)         // 200
#define OW (2 * Ww)         // 272
#define OHW (OH * OW)       // 54400
#define NP 169
#define MAXI 512
#define NBANDS 4            // output-row bands per instance (R13 proven)
#define BAND_OH 50          // output rows per band
#define MAX_ROWS 27         // max logit rows a band needs
#define NT 128              // threads per fused block (4 blocks/SM)

typedef unsigned long long ull;

// per-(instance,band) dice partials
__device__ float g_pi[MAXI * NBANDS];
__device__ float g_px[MAXI * NBANDS];
__device__ float g_pt[MAXI * NBANDS];

// ---- packed f32x2 helpers (sm_100+) ----
__device__ __forceinline__ ull pk2(float lo, float hi) {
    ull r; asm("mov.b64 %0, {%1,%2};" : "=l"(r) : "f"(lo), "f"(hi)); return r;
}
__device__ __forceinline__ ull dup2(float x) {
    ull r; asm("mov.b64 %0, {%1,%1};" : "=l"(r) : "f"(x)); return r;
}
__device__ __forceinline__ ull fma2(ull a, ull b, ull c) {
    ull d; asm("fma.rn.f32x2 %0, %1, %2, %3;" : "=l"(d) : "l"(a), "l"(b), "l"(c)); return d;
}
__device__ __forceinline__ ull relu2(ull a) {
    float x, y;
    asm("mov.b64 {%0,%1}, %2;" : "=f"(x), "=f"(y) : "l"(a));
    x = fmaxf(x, 0.0f); y = fmaxf(y, 0.0f);
    ull r; asm("mov.b64 %0, {%1,%2};" : "=l"(r) : "f"(x), "f"(y)); return r;
}
__device__ __forceinline__ void upk2(ull a, float& x, float& y) {
    asm("mov.b64 {%0,%1}, %2;" : "=f"(x), "=f"(y) : "l"(a));
}
__device__ __forceinline__ float tanh_fast(float x) {
    float r; asm("tanh.approx.f32 %0, %1;" : "=f"(r) : "f"(x)); return r;
}

// ---------------------------------------------------------------------------
// Fused kernel: one block = one (instance, band). 128 threads, 4 blocks/SM.
// Phase 1 (NEW packing): channel-pair accumulators (a_j,a_j+1) fed by packed
// weight pairs read straight from transposed float rows (1 LDS.128 = 4
// distinct weights) and duplicated activations (cheap mov.b64 {x,x}).
// Weight-LDS per quad: 89 -> ~45. fma2 count unchanged.
// Phase 2: 2x aligned bilinear + sigmoid(tanh) + dice, 16-px vectorized taps.
// ---------------------------------------------------------------------------
__global__ __launch_bounds__(NT, 4) void fused_kernel(
    const float* __restrict__ feats,
    const float* __restrict__ params,
    const float* __restrict__ locs,
    const int*   __restrict__ im_inds,
    const int*   __restrict__ fpn,
    const float* __restrict__ gt)
{
    const int inst = blockIdx.x >> 2;
    const int band = blockIdx.x & 3;
    const int tid  = threadIdx.x;

    extern __shared__ float sL[];              // MAX_ROWS * Ww floats

    // transposed weights, plain floats: consecutive j ARE the packed pairs
    __shared__ __align__(16) float st0[10][8];   // [c][j], c: 0=x,1=y,2..9=feat
    __shared__ __align__(16) float st1[8][8];    // [c][j]
    __shared__ __align__(16) float sw2f[8];
    __shared__ __align__(16) float sb0[8];
    __shared__ __align__(16) float sb1[8];
    __shared__ float sb2;

    for (int i = tid; i < NP; i += NT) {
        float w = params[inst * NP + i];
        if      (i < 80)  st0[i % 10][i / 10] = w;
        else if (i < 144) { int k = i - 80; st1[k & 7][k >> 3] = w; }
        else if (i < 152) sw2f[i - 144] = w;
        else if (i < 160) sb0[i - 152] = w;
        else if (i < 168) sb1[i - 160] = w;
        else              sb2 = w;
    }
    __syncthreads();

    // band geometry
    const int oy0  = band * BAND_OH;                       // first output row
    const int ry0  = (band > 0) ? (25 * band - 1) : 0;     // first logit row
    const int ry1  = (25 * band + 25 < Hh) ? (25 * band + 25) : (Hh - 1);
    const int nrows = ry1 - ry0 + 1;                       // 26 or 27

    const float cx = locs[inst * 2 + 0];
    const float cy = locs[inst * 2 + 1];
    const float inv_soi = 1.0f / (float)(8 << fpn[inst]);
    const float step = -8.0f * inv_soi;
    const float* __restrict__ fb = feats + (size_t)im_inds[inst] * 8 * HW;

    // ---------------- Phase 1: logits for rows [ry0..ry1] into SMEM --------
    const int NQ = nrows * (Ww / 4);        // <= 27*34 = 918 quads
    for (int q = tid; q < NQ; q += NT) {
        const int lr = q / (Ww / 4);
        const int px = (q - lr * (Ww / 4)) * 4;
        const int py = ry0 + lr;
        const int p  = py * Ww + px;
        const float dyv = (cy - (float)(py * 8 + 4)) * inv_soi;
        const float dxb = (cx - (float)(px * 8 + 4)) * inv_soi;

        // feature scalars per pixel
        float fv[4][8];
        #pragma unroll
        for (int c = 0; c < 8; c++) {
            float4 v = *(const float4*)&fb[c * HW + p];
            fv[0][c] = v.x; fv[1][c] = v.y; fv[2][c] = v.z; fv[3][c] = v.w;
        }

        // ---- layer 0: acc[k][t] = (a_{2t}, a_{2t+1}) for pixel k ----
        ull acc[4][4];
        {
            const ulonglong2* bb  = (const ulonglong2*)sb0;
            const ulonglong2* wxp = (const ulonglong2*)st0[0];
            const ulonglong2* wyp = (const ulonglong2*)st0[1];
            ulonglong2 b01 = bb[0],  b23 = bb[1];
            ulonglong2 wx0 = wxp[0], wx1 = wxp[1];
            ulonglong2 wy0 = wyp[0], wy1 = wyp[1];
            ull dyd = dup2(dyv);
            ull ty0 = fma2(wy0.x, dyd, b01.x);
            ull ty1 = fma2(wy0.y, dyd, b01.y);
            ull ty2 = fma2(wy1.x, dyd, b23.x);
            ull ty3 = fma2(wy1.y, dyd, b23.y);
            #pragma unroll
            for (int k = 0; k < 4; k++) {
                ull dxd = dup2(dxb + (float)k * step);
                acc[k][0] = fma2(wx0.x, dxd, ty0);
                acc[k][1] = fma2(wx0.y, dxd, ty1);
                acc[k][2] = fma2(wx1.x, dxd, ty2);
                acc[k][3] = fma2(wx1.y, dxd, ty3);
            }
        }
        #pragma unroll
        for (int c = 0; c < 8; c++) {
            const ulonglong2* wp = (const ulonglong2*)st0[c + 2];
            ulonglong2 w0 = wp[0], w1 = wp[1];
            #pragma unroll
            for (int k = 0; k < 4; k++) {
                ull fd = dup2(fv[k][c]);
                acc[k][0] = fma2(w0.x, fd, acc[k][0]);
                acc[k][1] = fma2(w0.y, fd, acc[k][1]);
                acc[k][2] = fma2(w1.x, fd, acc[k][2]);
                acc[k][3] = fma2(w1.y, fd, acc[k][3]);
            }
        }
        // relu + unpack to scalars
        float hs[4][8];
        #pragma unroll
        for (int k = 0; k < 4; k++)
            #pragma unroll
            for (int t = 0; t < 4; t++) {
                ull r = relu2(acc[k][t]);
                upk2(r, hs[k][2 * t], hs[k][2 * t + 1]);
            }

        // ---- layer 1 ----
        ull a1[4][4];
        {
            const ulonglong2* bb = (const ulonglong2*)sb1;
            ulonglong2 b01 = bb[0], b23 = bb[1];
            #pragma unroll
            for (int k = 0; k < 4; k++) {
                a1[k][0] = b01.x; a1[k][1] = b01.y;
                a1[k][2] = b23.x; a1[k][3] = b23.y;
            }
        }
        #pragma unroll
        for (int c = 0; c < 8; c++) {
            const ulonglong2* wp = (const ulonglong2*)st1[c];
            ulonglong2 w0 = wp[0], w1 = wp[1];
            #pragma unroll
            for (int k = 0; k < 4; k++) {
                ull hd = dup2(hs[k][c]);
                a1[k][0] = fma2(w0.x, hd, a1[k][0]);
                a1[k][1] = fma2(w0.y, hd, a1[k][1]);
                a1[k][2] = fma2(w1.x, hd, a1[k][2]);
                a1[k][3] = fma2(w1.y, hd, a1[k][3]);
            }
        }

        // ---- layer 2: horizontal pair-dot ----
        {
            const ulonglong2* wp = (const ulonglong2*)sw2f;
            ulonglong2 w0 = wp[0], w1 = wp[1];
            const float b2 = sb2;
            float o[4];
            #pragma unroll
            for (int k = 0; k < 4; k++) {
                ull s = fma2(w0.x, relu2(a1[k][0]), 0ull);   // (0.f,0.f) == 0ull
                s = fma2(w0.y, relu2(a1[k][1]), s);
                s = fma2(w1.x, relu2(a1[k][2]), s);
                s = fma2(w1.y, relu2(a1[k][3]), s);
                float lo, hi;
                upk2(s, lo, hi);
                o[k] = lo + hi + b2;
            }
            *(float4*)&sL[lr * Ww + px] = make_float4(o[0], o[1], o[2], o[3]);
        }

        // Anti-pipelining fence (R7 win: keeps regs bounded, no spill).
        asm volatile("" ::: "memory");
    }
    __syncthreads();

    // ---------------- Phase 2: bilinear + sigmoid + dice on the band -------
    const float* __restrict__ T = gt + (size_t)inst * OHW;
    float si = 0.0f, sx = 0.0f, st = 0.0f;

    const int NU = BAND_OH * (OW / 16);    // 50*17 = 850 units per block
    for (int u = tid; u < NU; u += NT) {
        const int r    = u / (OW / 16);
        const int ox16 = (u - r * (OW / 16)) * 16;
        const int oy   = oy0 + r;
        const int j    = (oy > 0) ? (oy - 1) : 0;
        const int y0g  = j >> 1;
        const float* r0 = sL + (y0g - ry0) * Ww;

        const int m0 = ox16 >> 1;                 // multiple of 8; m0+7 <= 135
        const int ml = (m0 > 0) ? m0 - 1 : 0;

        float t[9];                               // taps m0-1 .. m0+7
        if ((j & 1) == 0) {
            float4 a = *(const float4*)&r0[m0];
            float4 b = *(const float4*)&r0[m0 + 4];
            t[0] = r0[ml];
            t[1] = a.x; t[2] = a.y; t[3] = a.z; t[4] = a.w;
            t[5] = b.x; t[6] = b.y; t[7] = b.z; t[8] = b.w;
        } else {
            const int y1g = (y0g + 1 < Hh) ? y0g + 1 : Hh - 1;
            const float* r1 = sL + (y1g - ry0) * Ww;
            float4 a0 = *(const float4*)&r0[m0];
            float4 a1v = *(const float4*)&r1[m0];
            float4 b0 = *(const float4*)&r0[m0 + 4];
            float4 b1v = *(const float4*)&r1[m0 + 4];
            t[0] = 0.5f * (r0[ml] + r1[ml]);
            t[1] = 0.5f * (a0.x + a1v.x); t[2] = 0.5f * (a0.y + a1v.y);
            t[3] = 0.5f * (a0.z + a1v.z); t[4] = 0.5f * (a0.w + a1v.w);
            t[5] = 0.5f * (b0.x + b1v.x); t[6] = 0.5f * (b0.y + b1v.y);
            t[7] = 0.5f * (b0.z + b1v.z); t[8] = 0.5f * (b0.w + b1v.w);
        }

        float v[16];
        v[0] = (ox16 > 0) ? 0.5f * (t[0] + t[1]) : t[1];
        #pragma unroll
        for (int i = 1; i < 8; i++) v[2 * i] = 0.5f * (t[i] + t[i + 1]);
        #pragma unroll
        for (int i = 0; i < 8; i++) v[2 * i + 1] = t[i + 1];

        const int gbase = oy * OW + ox16;
        #pragma unroll
        for (int c = 0; c < 4; c++) {
            const float4 g = __ldcs((const float4*)&T[gbase + 4 * c]);
            const float tv[4] = { g.x, g.y, g.z, g.w };
            #pragma unroll
            for (int k = 0; k < 4; k++) {
                float s = fmaf(0.5f, tanh_fast(0.5f * v[4 * c + k]), 0.5f);
                si = fmaf(s, tv[k], si);
                sx = fmaf(s, s, sx);
                st = fmaf(tv[k], tv[k], st);
            }
        }
    }

    // block reduction (4 warps) -> per-(inst,band) partials
    __shared__ float sm[3][4];
    int lane = tid & 31;
    int wid  = tid >> 5;
    #pragma unroll
    for (int o = 16; o; o >>= 1) {
        si += __shfl_down_sync(0xffffffffu, si, o);
        sx += __shfl_down_sync(0xffffffffu, sx, o);
        st += __shfl_down_sync(0xffffffffu, st, o);
    }
    if (lane == 0) { sm[0][wid] = si; sm[1][wid] = sx; sm[2][wid] = st; }
    __syncthreads();
    if (wid == 0) {
        si = (lane < 4) ? sm[0][lane] : 0.0f;
        sx = (lane < 4) ? sm[1][lane] : 0.0f;
        st = (lane < 4) ? sm[2][lane] : 0.0f;
        #pragma unroll
        for (int o = 2; o; o >>= 1) {
            si += __shfl_down_sync(0xffffffffu, si, o);
            sx += __shfl_down_sync(0xffffffffu, sx, o);
            st += __shfl_down_sync(0xffffffffu, st, o);
        }
        if (lane == 0) {
            g_pi[blockIdx.x] = si;
            g_px[blockIdx.x] = sx;
            g_pt[blockIdx.x] = st;
        }
    }
}

// ---------------------------------------------------------------------------
// Loss: PDL — resident early, waits on the fused grid, then reduces.
// ---------------------------------------------------------------------------
__global__ __launch_bounds__(512) void loss_kernel(float* __restrict__ out, int n)
{
    cudaGridDependencySynchronize();   // PDL: wait for fused_kernel completion

    __shared__ float sm[16];
    float acc = 0.0f;
    for (int i = threadIdx.x; i < n; i += 512) {
        float si = 0.0f, sx = 0.0f, st = 0.0f;
        #pragma unroll
        for (int b = 0; b < NBANDS; b++) {
            si += g_pi[i * NBANDS + b];
            sx += g_px[i * NBANDS + b];
            st += g_pt[i * NBANDS + b];
        }
        float u = sx + st + 1e-5f;
        acc += 1.0f - 2.0f * si / u;
    }
    int lane = threadIdx.x & 31;
    int wid  = threadIdx.x >> 5;
    #pragma unroll
    for (int o = 16; o; o >>= 1) acc += __shfl_down_sync(0xffffffffu, acc, o);
    if (lane == 0) sm[wid] = acc;
    __syncthreads();
    if (wid == 0) {
        acc = (lane < 16) ? sm[lane] : 0.0f;
        #pragma unroll
        for (int o = 8; o; o >>= 1) acc += __shfl_down_sync(0xffffffffu, acc, o);
        if (lane == 0) out[0] = acc / (float)n;
    }
}

extern "C" void kernel_launch(void* const* d_in, const int* in_sizes, int n_in,
                              void* d_out, int out_size)
{
    const float* feats   = (const float*)d_in[0];
    const float* params  = (const float*)d_in[1];
    const float* locs    = (const float*)d_in[2];
    const float* gt      = (const float*)d_in[3];
    const int*   im_inds = (const int*)d_in[4];
    const int*   fpn     = (const int*)d_in[5];

    int n = in_sizes[1] / NP;
    if (n > MAXI) n = MAXI;

    const int smem = MAX_ROWS * Ww * (int)sizeof(float);   // 14688 B

    fused_kernel<<<NBANDS * n, NT, smem>>>(feats, params, locs, im_inds, fpn, gt);

    // PDL launch: loss_kernel becomes resident during fused tail.
    cudaLaunchConfig_t cfg = {};
    cfg.gridDim  = dim3(1, 1, 1);
    cfg.blockDim = dim3(512, 1, 1);
    cudaLaunchAttribute attr[1];
    attr[0].id = cudaLaunchAttributeProgrammaticStreamSerialization;
    attr[0].val.programmaticStreamSerializationAllowed = 1;
    cfg.attrs = attr;
    cfg.numAttrs = 1;
    cudaLaunchKernelEx(&cfg, loss_kernel, (float*)d_out, n);
}

// round 17
// speedup vs baseline: 1.2606x; 1.0005x over previous
#include <cuda_runtime.h>

#define Hh 100
#define Ww 136
#define HW (Hh * Ww)        // 13600
#define OH (2 * Hh)         // 200
#define OW (2 * Ww)         // 272
#define OHW (OH * OW)       // 54400
#define NP 169
#define MAXI 512
#define NBANDS 4            // output-row bands per instance
#define BAND_OH 50          // output rows per band
#define MAX_ROWS 27         // max logit rows a band needs
#define NT 128              // threads per fused block (4 blocks/SM)

typedef unsigned long long ull;

// per-(instance,band) dice partials
__device__ float g_pi[MAXI * NBANDS];
__device__ float g_px[MAXI * NBANDS];
__device__ float g_pt[MAXI * NBANDS];

// ---- packed f32x2 helpers (sm_100+) ----
__device__ __forceinline__ ull pk2(float lo, float hi) {
    ull r; asm("mov.b64 %0, {%1,%2};" : "=l"(r) : "f"(lo), "f"(hi)); return r;
}
__device__ __forceinline__ ull dup2(float x) {
    ull r; asm("mov.b64 %0, {%1,%1};" : "=l"(r) : "f"(x)); return r;
}
__device__ __forceinline__ ull fma2(ull a, ull b, ull c) {
    ull d; asm("fma.rn.f32x2 %0, %1, %2, %3;" : "=l"(d) : "l"(a), "l"(b), "l"(c)); return d;
}
__device__ __forceinline__ ull add2(ull a, ull b) {
    ull d; asm("add.rn.f32x2 %0, %1, %2;" : "=l"(d) : "l"(a), "l"(b)); return d;
}
__device__ __forceinline__ ull mul2(ull a, ull b) {
    ull d; asm("mul.rn.f32x2 %0, %1, %2;" : "=l"(d) : "l"(a), "l"(b)); return d;
}
__device__ __forceinline__ ull relu2(ull a) {
    float x, y;
    asm("mov.b64 {%0,%1}, %2;" : "=f"(x), "=f"(y) : "l"(a));
    x = fmaxf(x, 0.0f); y = fmaxf(y, 0.0f);
    ull r; asm("mov.b64 %0, {%1,%2};" : "=l"(r) : "f"(x), "f"(y)); return r;
}
__device__ __forceinline__ void upk2(ull a, float& x, float& y) {
    asm("mov.b64 {%0,%1}, %2;" : "=f"(x), "=f"(y) : "l"(a));
}
__device__ __forceinline__ float tanh_fast(float x) {
    float r; asm("tanh.approx.f32 %0, %1;" : "=f"(r) : "f"(x)); return r;
}

// ---------------------------------------------------------------------------
// Fused kernel: one block = one (instance, band). 128 threads, 4 blocks/SM.
// Phase 1: channel-pair packed MLP (R16 win).
// Phase 2: 16-px units; NEW: packed (f32x2) dice accumulation + packed
//          odd-row tap averaging.
// ---------------------------------------------------------------------------
__global__ __launch_bounds__(NT, 4) void fused_kernel(
    const float* __restrict__ feats,
    const float* __restrict__ params,
    const float* __restrict__ locs,
    const int*   __restrict__ im_inds,
    const int*   __restrict__ fpn,
    const float* __restrict__ gt)
{
    const int inst = blockIdx.x >> 2;
    const int band = blockIdx.x & 3;
    const int tid  = threadIdx.x;

    extern __shared__ float sL[];              // MAX_ROWS * Ww floats

    // transposed weights, plain floats: consecutive j ARE the packed pairs
    __shared__ __align__(16) float st0[10][8];   // [c][j], c: 0=x,1=y,2..9=feat
    __shared__ __align__(16) float st1[8][8];    // [c][j]
    __shared__ __align__(16) float sw2f[8];
    __shared__ __align__(16) float sb0[8];
    __shared__ __align__(16) float sb1[8];
    __shared__ float sb2;

    for (int i = tid; i < NP; i += NT) {
        float w = params[inst * NP + i];
        if      (i < 80)  st0[i % 10][i / 10] = w;
        else if (i < 144) { int k = i - 80; st1[k & 7][k >> 3] = w; }
        else if (i < 152) sw2f[i - 144] = w;
        else if (i < 160) sb0[i - 152] = w;
        else if (i < 168) sb1[i - 160] = w;
        else              sb2 = w;
    }
    __syncthreads();

    // band geometry
    const int oy0  = band * BAND_OH;                       // first output row
    const int ry0  = (band > 0) ? (25 * band - 1) : 0;     // first logit row
    const int ry1  = (25 * band + 25 < Hh) ? (25 * band + 25) : (Hh - 1);
    const int nrows = ry1 - ry0 + 1;                       // 26 or 27

    const float cx = locs[inst * 2 + 0];
    const float cy = locs[inst * 2 + 1];
    const float inv_soi = 1.0f / (float)(8 << fpn[inst]);
    const float step = -8.0f * inv_soi;
    const float* __restrict__ fb = feats + (size_t)im_inds[inst] * 8 * HW;

    // ---------------- Phase 1: logits for rows [ry0..ry1] into SMEM --------
    const int NQ = nrows * (Ww / 4);        // <= 27*34 = 918 quads
    for (int q = tid; q < NQ; q += NT) {
        const int lr = q / (Ww / 4);
        const int px = (q - lr * (Ww / 4)) * 4;
        const int py = ry0 + lr;
        const int p  = py * Ww + px;
        const float dyv = (cy - (float)(py * 8 + 4)) * inv_soi;
        const float dxb = (cx - (float)(px * 8 + 4)) * inv_soi;

        float fv[4][8];
        #pragma unroll
        for (int c = 0; c < 8; c++) {
            float4 v = *(const float4*)&fb[c * HW + p];
            fv[0][c] = v.x; fv[1][c] = v.y; fv[2][c] = v.z; fv[3][c] = v.w;
        }

        // ---- layer 0: acc[k][t] = (a_{2t}, a_{2t+1}) for pixel k ----
        ull acc[4][4];
        {
            const ulonglong2* bb  = (const ulonglong2*)sb0;
            const ulonglong2* wxp = (const ulonglong2*)st0[0];
            const ulonglong2* wyp = (const ulonglong2*)st0[1];
            ulonglong2 b01 = bb[0],  b23 = bb[1];
            ulonglong2 wx0 = wxp[0], wx1 = wxp[1];
            ulonglong2 wy0 = wyp[0], wy1 = wyp[1];
            ull dyd = dup2(dyv);
            ull ty0 = fma2(wy0.x, dyd, b01.x);
            ull ty1 = fma2(wy0.y, dyd, b01.y);
            ull ty2 = fma2(wy1.x, dyd, b23.x);
            ull ty3 = fma2(wy1.y, dyd, b23.y);
            #pragma unroll
            for (int k = 0; k < 4; k++) {
                ull dxd = dup2(dxb + (float)k * step);
                acc[k][0] = fma2(wx0.x, dxd, ty0);
                acc[k][1] = fma2(wx0.y, dxd, ty1);
                acc[k][2] = fma2(wx1.x, dxd, ty2);
                acc[k][3] = fma2(wx1.y, dxd, ty3);
            }
        }
        #pragma unroll
        for (int c = 0; c < 8; c++) {
            const ulonglong2* wp = (const ulonglong2*)st0[c + 2];
            ulonglong2 w0 = wp[0], w1 = wp[1];
            #pragma unroll
            for (int k = 0; k < 4; k++) {
                ull fd = dup2(fv[k][c]);
                acc[k][0] = fma2(w0.x, fd, acc[k][0]);
                acc[k][1] = fma2(w0.y, fd, acc[k][1]);
                acc[k][2] = fma2(w1.x, fd, acc[k][2]);
                acc[k][3] = fma2(w1.y, fd, acc[k][3]);
            }
        }
        float hs[4][8];
        #pragma unroll
        for (int k = 0; k < 4; k++)
            #pragma unroll
            for (int t = 0; t < 4; t++) {
                ull r = relu2(acc[k][t]);
                upk2(r, hs[k][2 * t], hs[k][2 * t + 1]);
            }

        // ---- layer 1 ----
        ull a1[4][4];
        {
            const ulonglong2* bb = (const ulonglong2*)sb1;
            ulonglong2 b01 = bb[0], b23 = bb[1];
            #pragma unroll
            for (int k = 0; k < 4; k++) {
                a1[k][0] = b01.x; a1[k][1] = b01.y;
                a1[k][2] = b23.x; a1[k][3] = b23.y;
            }
        }
        #pragma unroll
        for (int c = 0; c < 8; c++) {
            const ulonglong2* wp = (const ulonglong2*)st1[c];
            ulonglong2 w0 = wp[0], w1 = wp[1];
            #pragma unroll
            for (int k = 0; k < 4; k++) {
                ull hd = dup2(hs[k][c]);
                a1[k][0] = fma2(w0.x, hd, a1[k][0]);
                a1[k][1] = fma2(w0.y, hd, a1[k][1]);
                a1[k][2] = fma2(w1.x, hd, a1[k][2]);
                a1[k][3] = fma2(w1.y, hd, a1[k][3]);
            }
        }

        // ---- layer 2: horizontal pair-dot ----
        {
            const ulonglong2* wp = (const ulonglong2*)sw2f;
            ulonglong2 w0 = wp[0], w1 = wp[1];
            const float b2 = sb2;
            float o[4];
            #pragma unroll
            for (int k = 0; k < 4; k++) {
                ull s = fma2(w0.x, relu2(a1[k][0]), 0ull);
                s = fma2(w0.y, relu2(a1[k][1]), s);
                s = fma2(w1.x, relu2(a1[k][2]), s);
                s = fma2(w1.y, relu2(a1[k][3]), s);
                float lo, hi;
                upk2(s, lo, hi);
                o[k] = lo + hi + b2;
            }
            *(float4*)&sL[lr * Ww + px] = make_float4(o[0], o[1], o[2], o[3]);
        }

        asm volatile("" ::: "memory");   // anti-pipelining fence (R7 win)
    }
    __syncthreads();

    // ---------------- Phase 2: bilinear + sigmoid + dice on the band -------
    const float* __restrict__ T = gt + (size_t)inst * OHW;
    ull si2 = 0ull, sx2 = 0ull, st2 = 0ull;    // packed dice accumulators
    const ull half2d = pk2(0.5f, 0.5f);

    const int NU = BAND_OH * (OW / 16);    // 50*17 = 850 units per block
    for (int u = tid; u < NU; u += NT) {
        const int r    = u / (OW / 16);
        const int ox16 = (u - r * (OW / 16)) * 16;
        const int oy   = oy0 + r;
        const int j    = (oy > 0) ? (oy - 1) : 0;
        const int y0g  = j >> 1;
        const float* r0 = sL + (y0g - ry0) * Ww;

        const int m0 = ox16 >> 1;                 // multiple of 8; m0+7 <= 135
        const int ml = (m0 > 0) ? m0 - 1 : 0;

        float t[9];                               // taps m0-1 .. m0+7
        if ((j & 1) == 0) {
            float4 a = *(const float4*)&r0[m0];
            float4 b = *(const float4*)&r0[m0 + 4];
            t[0] = r0[ml];
            t[1] = a.x; t[2] = a.y; t[3] = a.z; t[4] = a.w;
            t[5] = b.x; t[6] = b.y; t[7] = b.z; t[8] = b.w;
        } else {
            const int y1g = (y0g + 1 < Hh) ? y0g + 1 : Hh - 1;
            const float* r1 = sL + (y1g - ry0) * Ww;
            // packed tap averaging: 0.5*(r0+r1) on register pairs
            ulonglong2 a0 = *(const ulonglong2*)&r0[m0];
            ulonglong2 a1v = *(const ulonglong2*)&r1[m0];
            ulonglong2 b0 = *(const ulonglong2*)&r0[m0 + 4];
            ulonglong2 b1v = *(const ulonglong2*)&r1[m0 + 4];
            ull p0 = mul2(add2(a0.x, a1v.x), half2d);
            ull p1 = mul2(add2(a0.y, a1v.y), half2d);
            ull p2 = mul2(add2(b0.x, b1v.x), half2d);
            ull p3 = mul2(add2(b0.y, b1v.y), half2d);
            t[0] = 0.5f * (r0[ml] + r1[ml]);
            upk2(p0, t[1], t[2]);
            upk2(p1, t[3], t[4]);
            upk2(p2, t[5], t[6]);
            upk2(p3, t[7], t[8]);
        }

        float v[16];
        v[0] = (ox16 > 0) ? 0.5f * (t[0] + t[1]) : t[1];
        #pragma unroll
        for (int i = 1; i < 8; i++) v[2 * i] = 0.5f * (t[i] + t[i + 1]);
        #pragma unroll
        for (int i = 0; i < 8; i++) v[2 * i + 1] = t[i + 1];

        const int gbase = oy * OW + ox16;
        #pragma unroll
        for (int c = 0; c < 4; c++) {
            const float4 g = __ldcs((const float4*)&T[gbase + 4 * c]);
            float s0 = fmaf(0.5f, tanh_fast(0.5f * v[4 * c + 0]), 0.5f);
            float s1 = fmaf(0.5f, tanh_fast(0.5f * v[4 * c + 1]), 0.5f);
            float s2 = fmaf(0.5f, tanh_fast(0.5f * v[4 * c + 2]), 0.5f);
            float s3 = fmaf(0.5f, tanh_fast(0.5f * v[4 * c + 3]), 0.5f);
            ull sp0 = pk2(s0, s1), sp1 = pk2(s2, s3);
            ull tp0 = pk2(g.x, g.y), tp1 = pk2(g.z, g.w);
            si2 = fma2(sp0, tp0, si2);
            si2 = fma2(sp1, tp1, si2);
            sx2 = fma2(sp0, sp0, sx2);
            sx2 = fma2(sp1, sp1, sx2);
            st2 = fma2(tp0, tp0, st2);
            st2 = fma2(tp1, tp1, st2);
        }
    }

    // unpack packed accumulators -> scalars
    float si, sx, st;
    {
        float a, b;
        upk2(si2, a, b); si = a + b;
        upk2(sx2, a, b); sx = a + b;
        upk2(st2, a, b); st = a + b;
    }

    // block reduction (4 warps) -> per-(inst,band) partials
    __shared__ float sm[3][4];
    int lane = tid & 31;
    int wid  = tid >> 5;
    #pragma unroll
    for (int o = 16; o; o >>= 1) {
        si += __shfl_down_sync(0xffffffffu, si, o);
        sx += __shfl_down_sync(0xffffffffu, sx, o);
        st += __shfl_down_sync(0xffffffffu, st, o);
    }
    if (lane == 0) { sm[0][wid] = si; sm[1][wid] = sx; sm[2][wid] = st; }
    __syncthreads();
    if (wid == 0) {
        si = (lane < 4) ? sm[0][lane] : 0.0f;
        sx = (lane < 4) ? sm[1][lane] : 0.0f;
        st = (lane < 4) ? sm[2][lane] : 0.0f;
        #pragma unroll
        for (int o = 2; o; o >>= 1) {
            si += __shfl_down_sync(0xffffffffu, si, o);
            sx += __shfl_down_sync(0xffffffffu, sx, o);
            st += __shfl_down_sync(0xffffffffu, st, o);
        }
        if (lane == 0) {
            g_pi[blockIdx.x] = si;
            g_px[blockIdx.x] = sx;
            g_pt[blockIdx.x] = st;
        }
    }
}

// ---------------------------------------------------------------------------
// Loss: PDL — resident early, waits on the fused grid, then reduces.
// ---------------------------------------------------------------------------
__global__ __launch_bounds__(512) void loss_kernel(float* __restrict__ out, int n)
{
    cudaGridDependencySynchronize();   // PDL: wait for fused_kernel completion

    __shared__ float sm[16];
    float acc = 0.0f;
    for (int i = threadIdx.x; i < n; i += 512) {
        float si = 0.0f, sx = 0.0f, st = 0.0f;
        #pragma unroll
        for (int b = 0; b < NBANDS; b++) {
            si += g_pi[i * NBANDS + b];
            sx += g_px[i * NBANDS + b];
            st += g_pt[i * NBANDS + b];
        }
        float u = sx + st + 1e-5f;
        acc += 1.0f - 2.0f * si / u;
    }
    int lane = threadIdx.x & 31;
    int wid  = threadIdx.x >> 5;
    #pragma unroll
    for (int o = 16; o; o >>= 1) acc += __shfl_down_sync(0xffffffffu, acc, o);
    if (lane == 0) sm[wid] = acc;
    __syncthreads();
    if (wid == 0) {
        acc = (lane < 16) ? sm[lane] : 0.0f;
        #pragma unroll
        for (int o = 8; o; o >>= 1) acc += __shfl_down_sync(0xffffffffu, acc, o);
        if (lane == 0) out[0] = acc / (float)n;
    }
}

extern "C" void kernel_launch(void* const* d_in, const int* in_sizes, int n_in,
                              void* d_out, int out_size)
{
    const float* feats   = (const float*)d_in[0];
    const float* params  = (const float*)d_in[1];
    const float* locs    = (const float*)d_in[2];
    const float* gt      = (const float*)d_in[3];
    const int*   im_inds = (const int*)d_in[4];
    const int*   fpn     = (const int*)d_in[5];

    int n = in_sizes[1] / NP;
    if (n > MAXI) n = MAXI;

    const int smem = MAX_ROWS * Ww * (int)sizeof(float);   // 14688 B

    fused_kernel<<<NBANDS * n, NT, smem>>>(feats, params, locs, im_inds, fpn, gt);

    // PDL launch: loss_kernel becomes resident during fused tail.
    cudaLaunchConfig_t cfg = {};
    cfg.gridDim  = dim3(1, 1, 1);
    cfg.blockDim = dim3(512, 1, 1);
    cudaLaunchAttribute attr[1];
    attr[0].id = cudaLaunchAttributeProgrammaticStreamSerialization;
    attr[0].val.programmaticStreamSerializationAllowed = 1;
    cfg.attrs = attr;
    cfg.numAttrs = 1;
    cudaLaunchKernelEx(&cfg, loss_kernel, (float*)d_out, n);
}